// round 11
// baseline (speedup 1.0000x reference)
#include <cuda_runtime.h>
#include <cuda_fp16.h>
#include <cstdint>

// ---------------- problem dims ----------------
#define M_DIM 4096
#define K_DIM 4096
#define N_DIM 16384

// ================= scratch (no cudaMalloc allowed) =================
__device__ __align__(256) __half g_A[(size_t)M_DIM * K_DIM];   // 32 MB fp16 x
__device__ __align__(256) __half g_B[(size_t)N_DIM * K_DIM];   // 128 MB fp16 w

// ---------------- helpers ----------------
__device__ __forceinline__ uint32_t smem_u32(const void* p) {
    uint32_t a;
    asm("{ .reg .u64 t; cvta.to.shared.u64 t, %1; cvt.u32.u64 %0, t; }"
        : "=r"(a) : "l"(p));
    return a;
}

#define SWZ128(x) ((x) ^ (((x) >> 3) & 0x70))

#define CP_ASYNC16(dst, src) \
    asm volatile("cp.async.cg.shared.global [%0], [%1], 16;" \
                 :: "r"((uint32_t)(dst)), "l"(src) : "memory")
#define CP_COMMIT() asm volatile("cp.async.commit_group;" ::: "memory")
#define CP_WAIT(n)  asm volatile("cp.async.wait_group %0;" :: "n"(n) : "memory")

#define LDMX4(r0, r1, r2, r3, addr) \
    asm volatile("ldmatrix.sync.aligned.m8n8.x4.shared.b16 {%0,%1,%2,%3}, [%4];" \
                 : "=r"(r0), "=r"(r1), "=r"(r2), "=r"(r3) : "r"(addr))

#define GROUP_BAR(id) \
    asm volatile("bar.sync %0, 128;" :: "r"(id) : "memory")

__device__ __forceinline__ void stcs16(void* p, uint4 v) {
    asm volatile("st.global.cs.v4.b32 [%0], {%1,%2,%3,%4};"
                 :: "l"(p), "r"(v.x), "r"(v.y), "r"(v.z), "r"(v.w) : "memory");
}
__device__ __forceinline__ void stcs8(void* p, float2 v) {
    asm volatile("st.global.cs.v2.f32 [%0], {%1,%2};"
                 :: "l"(p), "f"(v.x), "f"(v.y) : "memory");
}
// evict-first 16B load (touch-once streams: don't pollute L2)
__device__ __forceinline__ uint4 ldcs16(const void* p) {
    uint4 v;
    asm volatile("ld.global.cs.v4.b32 {%0,%1,%2,%3}, [%4];"
                 : "=r"(v.x), "=r"(v.y), "=r"(v.z), "=r"(v.w) : "l"(p));
    return v;
}

// ================= fused prepass =================
#define XB ((int)((size_t)M_DIM * K_DIM / 8 / 256))    // 8192
#define WB ((int)((size_t)N_DIM * K_DIM / 16 / 256))   // 16384

__global__ void __launch_bounds__(256) cvt_kernel(const float* __restrict__ x,
                                                  const int* __restrict__ w) {
    if (blockIdx.x < XB) {
        size_t gid = (size_t)blockIdx.x * 256 + threadIdx.x;
        uint4 u0 = ldcs16((const float4*)x + gid * 2);
        uint4 u1 = ldcs16((const float4*)x + gid * 2 + 1);
        float4 a = *(float4*)&u0, b = *(float4*)&u1;
        __half2 h0 = __floats2half2_rn(a.x, a.y);
        __half2 h1 = __floats2half2_rn(a.z, a.w);
        __half2 h2 = __floats2half2_rn(b.x, b.y);
        __half2 h3 = __floats2half2_rn(b.z, b.w);
        uint4 o;
        o.x = *(uint32_t*)&h0; o.y = *(uint32_t*)&h1;
        o.z = *(uint32_t*)&h2; o.w = *(uint32_t*)&h3;
        ((uint4*)g_A)[gid] = o;   // x-scratch: keep L2-resident (reused 64x)
    } else {
        size_t gid = (size_t)(blockIdx.x - XB) * 256 + threadIdx.x;
        const int4* s = (const int4*)w + gid * 4;
#pragma unroll
        for (int h = 0; h < 2; h++) {
            uint4 u0 = ldcs16(s + h * 2);
            uint4 u1 = ldcs16(s + h * 2 + 1);
            int4 v0 = *(int4*)&u0, v1 = *(int4*)&u1;
            __half2 p0 = __halves2half2(__float2half_rn((float)v0.x), __float2half_rn((float)v0.y));
            __half2 p1 = __halves2half2(__float2half_rn((float)v0.z), __float2half_rn((float)v0.w));
            __half2 p2 = __halves2half2(__float2half_rn((float)v1.x), __float2half_rn((float)v1.y));
            __half2 p3 = __halves2half2(__float2half_rn((float)v1.z), __float2half_rn((float)v1.w));
            uint4 o;
            o.x = *(uint32_t*)&p0; o.y = *(uint32_t*)&p1;
            o.z = *(uint32_t*)&p2; o.w = *(uint32_t*)&p3;
            stcs16((uint4*)g_B + gid * 2 + h, o);   // 128MB: evict-first
        }
    }
}

// =====================================================================
// GEMM: CTA = 128(M) x 256(N); two independent 128-thread groups, each a
// 128x128 N-half with its own 3-stage cp.async ring + named barrier.
// Per group: 4 warps (2M x 2N), warp tile 64x64, mma.sync.m16n8k16.
// kt loop manually unrolled x3 (compile-time stage addresses).
// Swizzle applied AFTER adding colb (SWZ128 is not linear).
// =====================================================================
#define G_TK 64
#define G_KTILES (K_DIM / G_TK)      // 64
#define GA_BYTES (128 * G_TK * 2)    // 16384
#define GB_BYTES (128 * G_TK * 2)    // 16384
#define G_STAGE (GA_BYTES + GB_BYTES)          // 32768
#define G_SMEM_PER (3 * G_STAGE)               // 98304
#define H_SMEM (2 * G_SMEM_PER)                // 196608

__global__ void __launch_bounds__(256, 1)
gemm_hmma(const float* __restrict__ scale, const float* __restrict__ bias,
          float* __restrict__ out) {
    extern __shared__ __align__(1024) char smem[];
    const int tid = threadIdx.x;
    const int lane = tid & 31;
    const int wid = tid >> 5;
    const int g = wid >> 2;            // group 0 / 1
    const int wg = wid & 3;
    const int wm = wg & 1;
    const int wn = wg >> 1;
    const int tg = tid & 127;
    const uint32_t sg = smem_u32(smem) + g * G_SMEM_PER;

    // tile rasterization: 8 consecutive CTAs share one tn
    const int nTN = N_DIM / 256;       // 64
    const int GROUPM = 8;
    const int npg = GROUPM * nTN;
    int pid = blockIdx.x;
    int grp = pid / npg;
    int inp = pid - grp * npg;
    int tm = grp * GROUPM + (inp % GROUPM);
    int tn = inp / GROUPM;

    const char* gA = (const char*)(g_A + (size_t)tm * 128 * K_DIM);
    const char* gB = (const char*)(g_B + ((size_t)tn * 256 + g * 128) * K_DIM);

    const int ld_row = tg >> 3;                 // 0..15 (+16 per i)
    const int ld_col = (tg & 7) * 16;

    // half-burst loaders (4 chunks each)
    auto load_A_half = [&](uint32_t sa, int kt, int h) {
        size_t kofs = (size_t)kt * 128;
#pragma unroll
        for (int i = 4 * h; i < 4 * h + 4; i++) {
            int row = ld_row + 16 * i;
            CP_ASYNC16(sa + SWZ128(row * 128 + ld_col),
                       gA + (size_t)row * (K_DIM * 2) + kofs + ld_col);
        }
    };
    auto load_B_full = [&](uint32_t sB, int kt) {
        size_t kofs = (size_t)kt * 128;
#pragma unroll
        for (int i = 0; i < 8; i++) {
            int row = ld_row + 16 * i;
            CP_ASYNC16(sB + SWZ128(row * 128 + ld_col),
                       gB + (size_t)row * (K_DIM * 2) + kofs + ld_col);
        }
    };

    float acc[4][8][4];
#pragma unroll
    for (int i = 0; i < 4; i++)
#pragma unroll
        for (int j = 0; j < 8; j++)
#pragma unroll
            for (int k = 0; k < 4; k++) acc[i][j][k] = 0.f;

    const int a_row = lane & 15;
    const int a_col = (lane >> 4) * 16;
    const int b_row = (lane & 7) + ((lane >> 4) << 3);
    const int b_col = ((lane >> 3) & 1) * 16;

    uint32_t a_base[4], b_base[4];
#pragma unroll
    for (int mt = 0; mt < 4; mt++)
        a_base[mt] = (wm * 64 + mt * 16 + a_row) * 128 + a_col;
#pragma unroll
    for (int nt2 = 0; nt2 < 4; nt2++)
        b_base[nt2] = (wn * 64 + nt2 * 16 + b_row) * 128 + b_col;

    auto do_ks = [&](uint32_t sa, uint32_t sB, int ks) {
        const uint32_t colb = ks * 32;
        uint32_t afr[4][4], bfr[4][4];
        LDMX4(afr[0][0], afr[0][1], afr[0][2], afr[0][3],
              sa + SWZ128(a_base[0] + colb));
#pragma unroll
        for (int nt2 = 0; nt2 < 4; nt2++)
            LDMX4(bfr[nt2][0], bfr[nt2][1], bfr[nt2][2], bfr[nt2][3],
                  sB + SWZ128(b_base[nt2] + colb));
#pragma unroll
        for (int mt = 1; mt < 4; mt++)
            LDMX4(afr[mt][0], afr[mt][1], afr[mt][2], afr[mt][3],
                  sa + SWZ128(a_base[mt] + colb));
#pragma unroll
        for (int mt = 0; mt < 4; mt++) {
#pragma unroll
            for (int nt = 0; nt < 8; nt++) {
                uint32_t b0 = (nt & 1) ? bfr[nt >> 1][2] : bfr[nt >> 1][0];
                uint32_t b1 = (nt & 1) ? bfr[nt >> 1][3] : bfr[nt >> 1][1];
                asm volatile(
                    "mma.sync.aligned.m16n8k16.row.col.f32.f16.f16.f32 "
                    "{%0,%1,%2,%3}, {%4,%5,%6,%7}, {%8,%9}, {%0,%1,%2,%3};"
                    : "+f"(acc[mt][nt][0]), "+f"(acc[mt][nt][1]),
                      "+f"(acc[mt][nt][2]), "+f"(acc[mt][nt][3])
                    : "r"(afr[mt][0]), "r"(afr[mt][1]),
                      "r"(afr[mt][2]), "r"(afr[mt][3]),
                      "r"(b0), "r"(b1));
            }
        }
    };

    const uint32_t st0 = sg, st1 = sg + G_STAGE, st2 = sg + 2 * G_STAGE;

    // prologue: fill stages 0 and 1
    load_A_half(st0, 0, 0); load_A_half(st0, 0, 1); load_B_full(st0 + GA_BYTES, 0); CP_COMMIT();
    load_A_half(st1, 1, 0); load_A_half(st1, 1, 1); load_B_full(st1 + GA_BYTES, 1); CP_COMMIT();

    auto iter = [&](int kt, uint32_t cur, uint32_t pre) {
        if (kt + 1 >= G_KTILES) { CP_WAIT(0); }
        else                    { CP_WAIT(1); }
        GROUP_BAR(1 + g);
        const uint32_t sa = cur, sB = cur + GA_BYTES;
        const bool pf = (kt + 2 < G_KTILES);
        do_ks(sa, sB, 0);
        if (pf) load_A_half(pre, kt + 2, 0);
        do_ks(sa, sB, 1);
        if (pf) load_A_half(pre, kt + 2, 1);
        do_ks(sa, sB, 2);
        if (pf) { load_B_full(pre + GA_BYTES, kt + 2); CP_COMMIT(); }
        do_ks(sa, sB, 3);
    };

    // main: kt 0..62 in triples, tail kt=63 (63 % 3 == 0 -> stage st0)
#pragma unroll 1
    for (int kt0 = 0; kt0 < 63; kt0 += 3) {
        iter(kt0 + 0, st0, st2);
        iter(kt0 + 1, st1, st0);
        iter(kt0 + 2, st2, st1);
    }
    iter(63, st0, st2);

    // ---- epilogue: fuse per-channel scale + bias, streaming stores ----
    const int ncol0 = tn * 256 + g * 128 + wn * 64;
    float2 sc2[8], bi2[8];
#pragma unroll
    for (int nt = 0; nt < 8; nt++) {
        int cn = ncol0 + nt * 8 + 2 * (lane & 3);
        sc2[nt] = *(const float2*)(scale + cn);
        bi2[nt] = *(const float2*)(bias + cn);
    }
#pragma unroll
    for (int mt = 0; mt < 4; mt++) {
        int r0 = tm * 128 + wm * 64 + mt * 16 + (lane >> 2);
        int r1 = r0 + 8;
#pragma unroll
        for (int nt = 0; nt < 8; nt++) {
            int cn = ncol0 + nt * 8 + 2 * (lane & 3);
            float2 o0, o1;
            o0.x = acc[mt][nt][0] * sc2[nt].x + bi2[nt].x;
            o0.y = acc[mt][nt][1] * sc2[nt].y + bi2[nt].y;
            o1.x = acc[mt][nt][2] * sc2[nt].x + bi2[nt].x;
            o1.y = acc[mt][nt][3] * sc2[nt].y + bi2[nt].y;
            stcs8(out + (size_t)r0 * N_DIM + cn, o0);
            stcs8(out + (size_t)r1 * N_DIM + cn, o1);
        }
    }
}

// ---------------- launch ----------------
extern "C" void kernel_launch(void* const* d_in, const int* in_sizes, int n_in,
                              void* d_out, int out_size) {
    const float* x     = (const float*)d_in[0];
    const int*   w     = (const int*)d_in[1];   // int8 values shipped as int32
    const float* scale = (const float*)d_in[2];
    const float* bias  = (const float*)d_in[3];
    float*       out   = (float*)d_out;

    cudaFuncSetAttribute(gemm_hmma,
                         cudaFuncAttributeMaxDynamicSharedMemorySize, H_SMEM);

    cvt_kernel<<<XB + WB, 256>>>(x, w);
    gemm_hmma<<<(M_DIM / 128) * (N_DIM / 256), 256, H_SMEM>>>(scale, bias, out);
}

// round 12
// speedup vs baseline: 1.0664x; 1.0664x over previous
#include <cuda_runtime.h>
#include <cuda_fp16.h>
#include <cstdint>

// ---------------- problem dims ----------------
#define M_DIM 4096
#define K_DIM 4096
#define N_DIM 16384

// ================= scratch (no cudaMalloc allowed) =================
__device__ __align__(256) __half g_A[(size_t)M_DIM * K_DIM];   // 32 MB fp16 x
__device__ __align__(256) __half g_B[(size_t)N_DIM * K_DIM];   // 128 MB fp16 w

// ---------------- helpers ----------------
__device__ __forceinline__ uint32_t smem_u32(const void* p) {
    uint32_t a;
    asm("{ .reg .u64 t; cvta.to.shared.u64 t, %1; cvt.u32.u64 %0, t; }"
        : "=r"(a) : "l"(p));
    return a;
}

#define SWZ128(x) ((x) ^ (((x) >> 3) & 0x70))

#define CP_ASYNC16(dst, src) \
    asm volatile("cp.async.cg.shared.global [%0], [%1], 16;" \
                 :: "r"((uint32_t)(dst)), "l"(src) : "memory")
#define CP_COMMIT() asm volatile("cp.async.commit_group;" ::: "memory")
#define CP_WAIT(n)  asm volatile("cp.async.wait_group %0;" :: "n"(n) : "memory")

#define LDMX4(r0, r1, r2, r3, addr) \
    asm volatile("ldmatrix.sync.aligned.m8n8.x4.shared.b16 {%0,%1,%2,%3}, [%4];" \
                 : "=r"(r0), "=r"(r1), "=r"(r2), "=r"(r3) : "r"(addr))

__device__ __forceinline__ void stcs16(void* p, uint4 v) {
    asm volatile("st.global.cs.v4.b32 [%0], {%1,%2,%3,%4};"
                 :: "l"(p), "r"(v.x), "r"(v.y), "r"(v.z), "r"(v.w) : "memory");
}
__device__ __forceinline__ void stcs8(void* p, float2 v) {
    asm volatile("st.global.cs.v2.f32 [%0], {%1,%2};"
                 :: "l"(p), "f"(v.x), "f"(v.y) : "memory");
}

// ================= fused prepass (default-policy loads; R11 ld.cs reverted) =================
#define XB ((int)((size_t)M_DIM * K_DIM / 8 / 256))    // 8192
#define WB ((int)((size_t)N_DIM * K_DIM / 16 / 256))   // 16384

__global__ void __launch_bounds__(256) cvt_kernel(const float* __restrict__ x,
                                                  const int* __restrict__ w) {
    if (blockIdx.x < XB) {
        size_t gid = (size_t)blockIdx.x * 256 + threadIdx.x;
        const float4* s = (const float4*)x + gid * 2;
        float4 a = s[0], b = s[1];
        __half2 h0 = __floats2half2_rn(a.x, a.y);
        __half2 h1 = __floats2half2_rn(a.z, a.w);
        __half2 h2 = __floats2half2_rn(b.x, b.y);
        __half2 h3 = __floats2half2_rn(b.z, b.w);
        uint4 o;
        o.x = *(uint32_t*)&h0; o.y = *(uint32_t*)&h1;
        o.z = *(uint32_t*)&h2; o.w = *(uint32_t*)&h3;
        ((uint4*)g_A)[gid] = o;   // x-scratch: keep L2-resident (reused 128x)
    } else {
        size_t gid = (size_t)(blockIdx.x - XB) * 256 + threadIdx.x;
        const int4* s = (const int4*)w + gid * 4;
#pragma unroll
        for (int h = 0; h < 2; h++) {
            int4 v0 = s[h * 2], v1 = s[h * 2 + 1];
            __half2 p0 = __halves2half2(__float2half_rn((float)v0.x), __float2half_rn((float)v0.y));
            __half2 p1 = __halves2half2(__float2half_rn((float)v0.z), __float2half_rn((float)v0.w));
            __half2 p2 = __halves2half2(__float2half_rn((float)v1.x), __float2half_rn((float)v1.y));
            __half2 p3 = __halves2half2(__float2half_rn((float)v1.z), __float2half_rn((float)v1.w));
            uint4 o;
            o.x = *(uint32_t*)&p0; o.y = *(uint32_t*)&p1;
            o.z = *(uint32_t*)&p2; o.w = *(uint32_t*)&p3;
            stcs16((uint4*)g_B + gid * 2 + h, o);   // 128MB: evict-first stores
        }
    }
}

// =====================================================================
// GEMM: CTA = 128 threads = ONE pipeline, tile 128(M) x 128(N).
// Occupancy 2 CTAs/SM (regs 255*128*2 = 65280, smem 2*96KB) -> the two
// pipelines on an SM are now separate CTAs: work replacement at tile
// boundaries is per-pipeline, and wave tails shrink.
// 4 warps (2M x 2N), warp tile 64x64, mma.sync.m16n8k16,
// 3-stage cp.async ring, kt-loop unrolled x3, 3-way split prefetch bursts.
// Swizzle applied AFTER adding colb (SWZ128 is not linear).
// =====================================================================
#define G_TK 64
#define G_KTILES (K_DIM / G_TK)      // 64
#define GA_BYTES (128 * G_TK * 2)    // 16384
#define GB_BYTES (128 * G_TK * 2)    // 16384
#define G_STAGE (GA_BYTES + GB_BYTES)          // 32768
#define H_SMEM (3 * G_STAGE)                   // 98304 per CTA

__global__ void __launch_bounds__(128, 2)
gemm_hmma(const float* __restrict__ scale, const float* __restrict__ bias,
          float* __restrict__ out) {
    extern __shared__ __align__(1024) char smem[];
    const int tid = threadIdx.x;          // 0..127
    const int lane = tid & 31;
    const int wid = tid >> 5;             // 0..3
    const int wm = wid & 1;               // 2 warps along M
    const int wn = wid >> 1;              // 2 warps along N
    const uint32_t sg = smem_u32(smem);

    // tile rasterization: 8 consecutive CTAs share one tn (B tile in L2)
    const int nTN = N_DIM / 128;          // 128
    const int GROUPM = 8;
    const int npg = GROUPM * nTN;         // 1024
    int pid = blockIdx.x;
    int grp = pid / npg;
    int inp = pid - grp * npg;
    int tm = grp * GROUPM + (inp % GROUPM);
    int tn = inp / GROUPM;

    const char* gA = (const char*)(g_A + (size_t)tm * 128 * K_DIM);
    const char* gB = (const char*)(g_B + (size_t)tn * 128 * K_DIM);

    const int ld_row = tid >> 3;          // 0..15 (+16 per i)
    const int ld_col = (tid & 7) * 16;

    auto load_A_half = [&](uint32_t sa, int kt, int h) {
        size_t kofs = (size_t)kt * 128;
#pragma unroll
        for (int i = 4 * h; i < 4 * h + 4; i++) {
            int row = ld_row + 16 * i;
            CP_ASYNC16(sa + SWZ128(row * 128 + ld_col),
                       gA + (size_t)row * (K_DIM * 2) + kofs + ld_col);
        }
    };
    auto load_B_full = [&](uint32_t sB, int kt) {
        size_t kofs = (size_t)kt * 128;
#pragma unroll
        for (int i = 0; i < 8; i++) {
            int row = ld_row + 16 * i;
            CP_ASYNC16(sB + SWZ128(row * 128 + ld_col),
                       gB + (size_t)row * (K_DIM * 2) + kofs + ld_col);
        }
    };

    float acc[4][8][4];
#pragma unroll
    for (int i = 0; i < 4; i++)
#pragma unroll
        for (int j = 0; j < 8; j++)
#pragma unroll
            for (int k = 0; k < 4; k++) acc[i][j][k] = 0.f;

    const int a_row = lane & 15;
    const int a_col = (lane >> 4) * 16;
    const int b_row = (lane & 7) + ((lane >> 4) << 3);
    const int b_col = ((lane >> 3) & 1) * 16;

    uint32_t a_base[4], b_base[4];
#pragma unroll
    for (int mt = 0; mt < 4; mt++)
        a_base[mt] = (wm * 64 + mt * 16 + a_row) * 128 + a_col;
#pragma unroll
    for (int nt2 = 0; nt2 < 4; nt2++)
        b_base[nt2] = (wn * 64 + nt2 * 16 + b_row) * 128 + b_col;

    auto do_ks = [&](uint32_t sa, uint32_t sB, int ks) {
        const uint32_t colb = ks * 32;
        uint32_t afr[4][4], bfr[4][4];
        LDMX4(afr[0][0], afr[0][1], afr[0][2], afr[0][3],
              sa + SWZ128(a_base[0] + colb));
#pragma unroll
        for (int nt2 = 0; nt2 < 4; nt2++)
            LDMX4(bfr[nt2][0], bfr[nt2][1], bfr[nt2][2], bfr[nt2][3],
                  sB + SWZ128(b_base[nt2] + colb));
#pragma unroll
        for (int mt = 1; mt < 4; mt++)
            LDMX4(afr[mt][0], afr[mt][1], afr[mt][2], afr[mt][3],
                  sa + SWZ128(a_base[mt] + colb));
#pragma unroll
        for (int mt = 0; mt < 4; mt++) {
#pragma unroll
            for (int nt = 0; nt < 8; nt++) {
                uint32_t b0 = (nt & 1) ? bfr[nt >> 1][2] : bfr[nt >> 1][0];
                uint32_t b1 = (nt & 1) ? bfr[nt >> 1][3] : bfr[nt >> 1][1];
                asm volatile(
                    "mma.sync.aligned.m16n8k16.row.col.f32.f16.f16.f32 "
                    "{%0,%1,%2,%3}, {%4,%5,%6,%7}, {%8,%9}, {%0,%1,%2,%3};"
                    : "+f"(acc[mt][nt][0]), "+f"(acc[mt][nt][1]),
                      "+f"(acc[mt][nt][2]), "+f"(acc[mt][nt][3])
                    : "r"(afr[mt][0]), "r"(afr[mt][1]),
                      "r"(afr[mt][2]), "r"(afr[mt][3]),
                      "r"(b0), "r"(b1));
            }
        }
    };

    const uint32_t st0 = sg, st1 = sg + G_STAGE, st2 = sg + 2 * G_STAGE;

    // prologue: fill stages 0 and 1
    load_A_half(st0, 0, 0); load_A_half(st0, 0, 1); load_B_full(st0 + GA_BYTES, 0); CP_COMMIT();
    load_A_half(st1, 1, 0); load_A_half(st1, 1, 1); load_B_full(st1 + GA_BYTES, 1); CP_COMMIT();

    auto iter = [&](int kt, uint32_t cur, uint32_t pre) {
        if (kt + 1 >= G_KTILES) { CP_WAIT(0); }
        else                    { CP_WAIT(1); }
        __syncthreads();
        const uint32_t sa = cur, sB = cur + GA_BYTES;
        const bool pf = (kt + 2 < G_KTILES);
        do_ks(sa, sB, 0);
        if (pf) load_A_half(pre, kt + 2, 0);
        do_ks(sa, sB, 1);
        if (pf) load_A_half(pre, kt + 2, 1);
        do_ks(sa, sB, 2);
        if (pf) { load_B_full(pre + GA_BYTES, kt + 2); CP_COMMIT(); }
        do_ks(sa, sB, 3);
    };

    // main: kt 0..62 in triples, tail kt=63 (63 % 3 == 0 -> stage st0)
#pragma unroll 1
    for (int kt0 = 0; kt0 < 63; kt0 += 3) {
        iter(kt0 + 0, st0, st2);
        iter(kt0 + 1, st1, st0);
        iter(kt0 + 2, st2, st1);
    }
    iter(63, st0, st2);

    // ---- epilogue: fuse per-channel scale + bias, streaming stores ----
    const int ncol0 = tn * 128 + wn * 64;
    float2 sc2[8], bi2[8];
#pragma unroll
    for (int nt = 0; nt < 8; nt++) {
        int cn = ncol0 + nt * 8 + 2 * (lane & 3);
        sc2[nt] = *(const float2*)(scale + cn);
        bi2[nt] = *(const float2*)(bias + cn);
    }
#pragma unroll
    for (int mt = 0; mt < 4; mt++) {
        int r0 = tm * 128 + wm * 64 + mt * 16 + (lane >> 2);
        int r1 = r0 + 8;
#pragma unroll
        for (int nt = 0; nt < 8; nt++) {
            int cn = ncol0 + nt * 8 + 2 * (lane & 3);
            float2 o0, o1;
            o0.x = acc[mt][nt][0] * sc2[nt].x + bi2[nt].x;
            o0.y = acc[mt][nt][1] * sc2[nt].y + bi2[nt].y;
            o1.x = acc[mt][nt][2] * sc2[nt].x + bi2[nt].x;
            o1.y = acc[mt][nt][3] * sc2[nt].y + bi2[nt].y;
            stcs8(out + (size_t)r0 * N_DIM + cn, o0);
            stcs8(out + (size_t)r1 * N_DIM + cn, o1);
        }
    }
}

// ---------------- launch ----------------
extern "C" void kernel_launch(void* const* d_in, const int* in_sizes, int n_in,
                              void* d_out, int out_size) {
    const float* x     = (const float*)d_in[0];
    const int*   w     = (const int*)d_in[1];   // int8 values shipped as int32
    const float* scale = (const float*)d_in[2];
    const float* bias  = (const float*)d_in[3];
    float*       out   = (float*)d_out;

    cudaFuncSetAttribute(gemm_hmma,
                         cudaFuncAttributeMaxDynamicSharedMemorySize, H_SMEM);

    cvt_kernel<<<XB + WB, 256>>>(x, w);
    gemm_hmma<<<(M_DIM / 128) * (N_DIM / 128), 128, H_SMEM>>>(scale, bias, out);
}